// round 3
// baseline (speedup 1.0000x reference)
#include <cuda_runtime.h>
#include <cstdint>
#include <math.h>

#define Bn 32768
#define Gn 2048
#define Hn 512
#define An 8
#define PH 64
#define HH 32
#define KE 576      // 64 (hid) + 512 (h_prev)
#define NE 2048     // [r_sum | z_sum | i_n | h_n]

// ---------------- device scratch (no runtime allocation allowed) ----------------
__device__ float g_Wext[KE * NE];          // 4.7 MB folded weight
__device__ float g_bias[NE];
__device__ float g_hid[Bn * PH];           // 8 MB
__device__ float g_G[(size_t)Bn * NE];     // 256 MB gate pre-activations

// ---------------- helpers ----------------
__device__ __forceinline__ uint32_t f2tf(float f) {
    uint32_t r;
    asm("cvt.rna.tf32.f32 %0, %1;" : "=r"(r) : "f"(f));
    return r;
}

__device__ __forceinline__ void mma_tf32(float* d, const uint32_t* a, const uint32_t* b) {
    asm volatile(
        "mma.sync.aligned.m16n8k8.row.col.f32.tf32.tf32.f32 "
        "{%0,%1,%2,%3},{%4,%5,%6,%7},{%8,%9},{%0,%1,%2,%3};"
        : "+f"(d[0]), "+f"(d[1]), "+f"(d[2]), "+f"(d[3])
        : "r"(a[0]), "r"(a[1]), "r"(a[2]), "r"(a[3]), "r"(b[0]), "r"(b[1]));
}

// ---------------- fold kernels (run every launch; cheap) ----------------
// W_ext[p, j] = sum_h proj_w1[p,h] * w_ih[j,h]   for p<64, j<1536 ; 0 for j>=1536
__global__ void fold_wc_kernel(const float* __restrict__ w1, const float* __restrict__ wih) {
    __shared__ float As[64][64];   // proj_w1 tile (reads are warp-uniform broadcasts)
    __shared__ float Bs[64][65];   // w_ih tile transposed: Bs[k][n]
    int t = threadIdx.x;
    int n0 = blockIdx.x * 64;
    if (n0 >= 1536) {
        for (int i = t; i < 64 * 64; i += 256) {
            int p = i >> 6, j = i & 63;
            g_Wext[p * NE + n0 + j] = 0.f;
        }
        return;
    }
    int nlane = t & 63;
    int pset = t >> 6;  // uniform per warp
    float acc[16];
#pragma unroll
    for (int i = 0; i < 16; ++i) acc[i] = 0.f;

    for (int kt = 0; kt < 512; kt += 64) {
        for (int i = t * 4; i < 64 * 64; i += 1024) {
            int p = i >> 6, c = i & 63;
            float4 v = *(const float4*)(w1 + p * 512 + kt + c);
            *(float4*)&As[p][c] = v;
        }
        for (int i = t * 4; i < 64 * 64; i += 1024) {
            int r = i >> 6, c = i & 63;
            float4 v = *(const float4*)(wih + (size_t)(n0 + r) * 512 + kt + c);
            Bs[c + 0][r] = v.x; Bs[c + 1][r] = v.y; Bs[c + 2][r] = v.z; Bs[c + 3][r] = v.w;
        }
        __syncthreads();
#pragma unroll 8
        for (int k = 0; k < 64; ++k) {
            float bv = Bs[k][nlane];
#pragma unroll
            for (int pp = 0; pp < 16; ++pp)
                acc[pp] += As[pset * 16 + pp][k] * bv;
        }
        __syncthreads();
    }
#pragma unroll
    for (int pp = 0; pp < 16; ++pp)
        g_Wext[(pset * 16 + pp) * NE + n0 + nlane] = acc[pp];
}

// W_ext[64+k, j] = w_hh[src_j, k]; zero for j in [1024,1536)
__global__ void fold_hh_kernel(const float* __restrict__ whh) {
    __shared__ float s[32][33];
    int j0 = blockIdx.x * 32;  // output column
    int k0 = blockIdx.y * 32;  // k row
    int tx = threadIdx.x, ty = threadIdx.y;
    bool zero = (j0 >= 1024 && j0 < 1536);
    int srcbase = (j0 < 1024) ? j0 : j0 - 512;
    if (!zero) {
        for (int r = ty; r < 32; r += 8)
            s[r][tx] = whh[(size_t)(srcbase + r) * 512 + k0 + tx];
        __syncthreads();
        for (int r = ty; r < 32; r += 8)
            g_Wext[(size_t)(64 + k0 + r) * NE + j0 + tx] = s[tx][r];
    } else {
        for (int r = ty; r < 32; r += 8)
            g_Wext[(size_t)(64 + k0 + r) * NE + j0 + tx] = 0.f;
    }
}

__global__ void fold_bias_kernel(const float* __restrict__ wih, const float* __restrict__ pb1,
                                 const float* __restrict__ bih, const float* __restrict__ bhh) {
    int col = blockIdx.x * 256 + threadIdx.x;
    if (col >= NE) return;
    float v;
    if (col < 1536) {
        float s = 0.f;
        for (int h = 0; h < 512; ++h) s += pb1[h] * wih[(size_t)col * 512 + h];
        float bc = bih[col] + s;
        v = (col < 1024) ? (bc + bhh[col]) : bc;
    } else {
        v = bhh[col - 512];
    }
    g_bias[col] = v;
}

// ---------------- GEMM1: hid = relu(obs @ w0 + b0)  [32768,2048]x[2048,64] ----------------
__global__ __launch_bounds__(128) void gemm1_kernel(const float* __restrict__ obs,
                                                    const float* __restrict__ w0,
                                                    const float* __restrict__ b0) {
    __shared__ uint32_t As[64][36];   // (4g+c) bank pattern -> conflict free frag loads
    __shared__ uint32_t Bs[32][72];   // (8c+g) bank pattern
    int t = threadIdx.x;
    int lane = t & 31, warp = t >> 5;
    int g = lane >> 2, c = lane & 3;
    int wm = warp >> 1, wn = warp & 1;
    int m0 = blockIdx.y * 64;

    float acc[2][4][4];
#pragma unroll
    for (int i = 0; i < 2; ++i)
#pragma unroll
        for (int j = 0; j < 4; ++j)
#pragma unroll
            for (int k = 0; k < 4; ++k) acc[i][j][k] = 0.f;

    for (int kt = 0; kt < Gn; kt += 32) {
#pragma unroll
        for (int p = 0; p < 4; ++p) {
            int row = p * 16 + (t >> 3);
            int k4 = (t & 7) * 4;
            float4 v = *(const float4*)(obs + (size_t)(m0 + row) * Gn + kt + k4);
            As[row][k4 + 0] = f2tf(v.x); As[row][k4 + 1] = f2tf(v.y);
            As[row][k4 + 2] = f2tf(v.z); As[row][k4 + 3] = f2tf(v.w);
        }
#pragma unroll
        for (int p = 0; p < 4; ++p) {
            int k = p * 8 + (t >> 4);
            int n4 = (t & 15) * 4;
            float4 v = *(const float4*)(w0 + (size_t)(kt + k) * 64 + n4);
            Bs[k][n4 + 0] = f2tf(v.x); Bs[k][n4 + 1] = f2tf(v.y);
            Bs[k][n4 + 2] = f2tf(v.z); Bs[k][n4 + 3] = f2tf(v.w);
        }
        __syncthreads();
#pragma unroll
        for (int kk = 0; kk < 4; ++kk) {
            uint32_t af[2][4], bf[4][2];
#pragma unroll
            for (int fm = 0; fm < 2; ++fm) {
                int r = wm * 32 + fm * 16;
                af[fm][0] = As[r + g][kk * 8 + c];
                af[fm][1] = As[r + g + 8][kk * 8 + c];
                af[fm][2] = As[r + g][kk * 8 + c + 4];
                af[fm][3] = As[r + g + 8][kk * 8 + c + 4];
            }
#pragma unroll
            for (int fn = 0; fn < 4; ++fn) {
                int cb = wn * 32 + fn * 8;
                bf[fn][0] = Bs[kk * 8 + c][cb + g];
                bf[fn][1] = Bs[kk * 8 + c + 4][cb + g];
            }
#pragma unroll
            for (int fm = 0; fm < 2; ++fm)
#pragma unroll
                for (int fn = 0; fn < 4; ++fn)
                    mma_tf32(acc[fm][fn], af[fm], bf[fn]);
        }
        __syncthreads();
    }
#pragma unroll
    for (int fm = 0; fm < 2; ++fm) {
        int row = m0 + wm * 32 + fm * 16 + g;
#pragma unroll
        for (int fn = 0; fn < 4; ++fn) {
            int col = wn * 32 + fn * 8 + c * 2;
            float bA = b0[col], bB = b0[col + 1];
            float2 v0 = make_float2(fmaxf(acc[fm][fn][0] + bA, 0.f), fmaxf(acc[fm][fn][1] + bB, 0.f));
            float2 v1 = make_float2(fmaxf(acc[fm][fn][2] + bA, 0.f), fmaxf(acc[fm][fn][3] + bB, 0.f));
            *(float2*)(g_hid + (size_t)row * PH + col) = v0;
            *(float2*)(g_hid + (size_t)(row + 8) * PH + col) = v1;
        }
    }
}

// ---------------- GEMM2: G = [hid | h_prev] @ W_ext + bias  M=32768 N=2048 K=576 ----------------
__global__ __launch_bounds__(256) void gemm2_kernel(const float* __restrict__ hprev) {
    __shared__ uint32_t As[128][36];
    __shared__ uint32_t Bs[32][136];
    int t = threadIdx.x;
    int lane = t & 31, warp = t >> 5;
    int g = lane >> 2, c = lane & 3;
    int wm = warp >> 2, wn = warp & 3;  // 2 x 4 warp grid, warp tile 64x32
    int m0 = blockIdx.y * 128;
    int n0 = blockIdx.x * 128;

    float acc[4][4][4];
#pragma unroll
    for (int i = 0; i < 4; ++i)
#pragma unroll
        for (int j = 0; j < 4; ++j)
#pragma unroll
            for (int k = 0; k < 4; ++k) acc[i][j][k] = 0.f;

    for (int kt = 0; kt < KE; kt += 32) {
#pragma unroll
        for (int p = 0; p < 4; ++p) {
            int row = p * 32 + (t >> 3);
            int k4 = (t & 7) * 4;
            int gk = kt + k4;
            float4 v;
            if (gk < PH)
                v = *(const float4*)(g_hid + (size_t)(m0 + row) * PH + gk);
            else
                v = *(const float4*)(hprev + (size_t)(m0 + row) * Hn + (gk - PH));
            As[row][k4 + 0] = f2tf(v.x); As[row][k4 + 1] = f2tf(v.y);
            As[row][k4 + 2] = f2tf(v.z); As[row][k4 + 3] = f2tf(v.w);
        }
#pragma unroll
        for (int p = 0; p < 4; ++p) {
            int k = p * 8 + (t >> 5);
            int nn = (t & 31) * 4;
            float4 v = *(const float4*)(g_Wext + (size_t)(kt + k) * NE + n0 + nn);
            Bs[k][nn + 0] = f2tf(v.x); Bs[k][nn + 1] = f2tf(v.y);
            Bs[k][nn + 2] = f2tf(v.z); Bs[k][nn + 3] = f2tf(v.w);
        }
        __syncthreads();
#pragma unroll
        for (int kk = 0; kk < 4; ++kk) {
            uint32_t af[4][4], bf[4][2];
#pragma unroll
            for (int fm = 0; fm < 4; ++fm) {
                int r = wm * 64 + fm * 16;
                af[fm][0] = As[r + g][kk * 8 + c];
                af[fm][1] = As[r + g + 8][kk * 8 + c];
                af[fm][2] = As[r + g][kk * 8 + c + 4];
                af[fm][3] = As[r + g + 8][kk * 8 + c + 4];
            }
#pragma unroll
            for (int fn = 0; fn < 4; ++fn) {
                int cb = wn * 32 + fn * 8;
                bf[fn][0] = Bs[kk * 8 + c][cb + g];
                bf[fn][1] = Bs[kk * 8 + c + 4][cb + g];
            }
#pragma unroll
            for (int fm = 0; fm < 4; ++fm)
#pragma unroll
                for (int fn = 0; fn < 4; ++fn)
                    mma_tf32(acc[fm][fn], af[fm], bf[fn]);
        }
        __syncthreads();
    }
#pragma unroll
    for (int fm = 0; fm < 4; ++fm) {
        int row = m0 + wm * 64 + fm * 16 + g;
#pragma unroll
        for (int fn = 0; fn < 4; ++fn) {
            int col = n0 + wn * 32 + fn * 8 + c * 2;
            float bA = g_bias[col], bB = g_bias[col + 1];
            float2 v0 = make_float2(acc[fm][fn][0] + bA, acc[fm][fn][1] + bB);
            float2 v1 = make_float2(acc[fm][fn][2] + bA, acc[fm][fn][3] + bB);
            *(float2*)(g_G + (size_t)row * NE + col) = v0;
            *(float2*)(g_G + (size_t)(row + 8) * NE + col) = v1;
        }
    }
}

// ---------------- gates: h = (1-z)*n + z*h_prev ----------------
__device__ __forceinline__ float gatef(float pr, float pz, float pin, float phn, float hp) {
    float r = 1.f / (1.f + __expf(-pr));
    float z = 1.f / (1.f + __expf(-pz));
    float n = tanhf(pin + r * phn);
    return (1.f - z) * n + z * hp;
}

__global__ __launch_bounds__(256) void gates_kernel(const float* __restrict__ hprev,
                                                    float* __restrict__ hout) {
    int i = blockIdx.x * 256 + threadIdx.x;  // Bn*128 threads
    int b = i >> 7;
    int j = (i & 127) << 2;
    const float* row = g_G + (size_t)b * NE;
    float4 xr = *(const float4*)(row + j);
    float4 xz = *(const float4*)(row + 512 + j);
    float4 xi = *(const float4*)(row + 1024 + j);
    float4 xh = *(const float4*)(row + 1536 + j);
    float4 hp = *(const float4*)(hprev + (size_t)b * Hn + j);
    float4 o;
    o.x = gatef(xr.x, xz.x, xi.x, xh.x, hp.x);
    o.y = gatef(xr.y, xz.y, xi.y, xh.y, hp.y);
    o.z = gatef(xr.z, xz.z, xi.z, xh.z, hp.z);
    o.w = gatef(xr.w, xz.w, xi.w, xh.w, hp.w);
    *(float4*)(hout + (size_t)b * Hn + j) = o;
}

// ---------------- heads: per-sample agent head, smem-staged weights ----------------
__global__ __launch_bounds__(256) void heads_kernel(const float* __restrict__ h,
                                                    const int* __restrict__ aid,
                                                    const float* __restrict__ w1,
                                                    const float* __restrict__ b1,
                                                    const float* __restrict__ w2,
                                                    const float* __restrict__ b2,
                                                    float* __restrict__ out) {
    extern __shared__ float sm[];
    float* hs = sm;                 // 64 x 512
    float* w1s = sm + 64 * Hn;      // 512 x 32
    __shared__ int s_aid[64];
    __shared__ int s_list[64];
    __shared__ int s_cnt;
    int t = threadIdx.x, lane = t & 31, warp = t >> 5;
    int b0 = blockIdx.x * 64;

    {
        const float4* src = (const float4*)(h + (size_t)b0 * Hn);
        float4* dst = (float4*)hs;
        for (int i = t; i < 64 * 128; i += 256) dst[i] = src[i];
    }
    if (t < 64) s_aid[t] = aid[b0 + t];
    __syncthreads();

    for (int a = 0; a < An; ++a) {
        if (t == 0) s_cnt = 0;
        __syncthreads();
        if (t < 64 && s_aid[t] == a) {
            int p = atomicAdd(&s_cnt, 1);
            s_list[p] = t;
        }
        __syncthreads();
        int cnt = s_cnt;
        if (cnt > 0) {
            const float4* wsrc = (const float4*)(w1 + (size_t)a * Hn * HH);
            float4* wdst = (float4*)w1s;
            for (int i = t; i < Hn * HH / 4; i += 256) wdst[i] = wsrc[i];
            __syncthreads();
            float w2v = w2[a * 32 + lane];
            float b1v = b1[a * 32 + lane];
            float b2v = b2[a];
            for (int s = warp * 2; s < cnt; s += 16) {
                int l0 = s_list[s];
                bool has1 = (s + 1 < cnt);
                int l1 = has1 ? s_list[s + 1] : l0;
                const float4* r0 = (const float4*)(hs + l0 * Hn);
                const float4* r1 = (const float4*)(hs + l1 * Hn);
                float a0 = 0.f, a1 = 0.f;
#pragma unroll 8
                for (int hq = 0; hq < 128; ++hq) {
                    float4 x0 = r0[hq];
                    float4 x1 = r1[hq];
                    float wv0 = w1s[(hq * 4 + 0) * 32 + lane];
                    float wv1 = w1s[(hq * 4 + 1) * 32 + lane];
                    float wv2 = w1s[(hq * 4 + 2) * 32 + lane];
                    float wv3 = w1s[(hq * 4 + 3) * 32 + lane];
                    a0 = fmaf(x0.x, wv0, a0); a0 = fmaf(x0.y, wv1, a0);
                    a0 = fmaf(x0.z, wv2, a0); a0 = fmaf(x0.w, wv3, a0);
                    a1 = fmaf(x1.x, wv0, a1); a1 = fmaf(x1.y, wv1, a1);
                    a1 = fmaf(x1.z, wv2, a1); a1 = fmaf(x1.w, wv3, a1);
                }
                float v0 = fmaxf(a0 + b1v, 0.f) * w2v;
                float v1 = fmaxf(a1 + b1v, 0.f) * w2v;
#pragma unroll
                for (int off = 16; off; off >>= 1) {
                    v0 += __shfl_xor_sync(0xFFFFFFFFu, v0, off);
                    v1 += __shfl_xor_sync(0xFFFFFFFFu, v1, off);
                }
                if (lane == 0) {
                    out[b0 + l0] = v0 + b2v;
                    if (has1) out[b0 + l1] = v1 + b2v;
                }
            }
            __syncthreads();
        } else {
            __syncthreads();
        }
    }
}

// ---------------- launch ----------------
extern "C" void kernel_launch(void* const* d_in, const int* in_sizes, int n_in,
                              void* d_out, int out_size) {
    const float* obs   = (const float*)d_in[0];
    const float* hprev = (const float*)d_in[1];   // [1,B,H]
    const int*   aid   = (const int*)d_in[2];
    const float* pw0   = (const float*)d_in[3];
    const float* pb0   = (const float*)d_in[4];
    const float* pw1   = (const float*)d_in[5];
    const float* pb1   = (const float*)d_in[6];
    const float* wih   = (const float*)d_in[7];
    const float* whh   = (const float*)d_in[8];
    const float* bih   = (const float*)d_in[9];
    const float* bhh   = (const float*)d_in[10];
    const float* hw1   = (const float*)d_in[11];
    const float* hb1   = (const float*)d_in[12];
    const float* hw2   = (const float*)d_in[13];
    const float* hb2   = (const float*)d_in[14];

    float* out  = (float*)d_out;
    float* hout = out + Bn;  // h_critic_next region

    cudaFuncSetAttribute(heads_kernel, cudaFuncAttributeMaxDynamicSharedMemorySize, 196608);

    fold_wc_kernel<<<NE / 64, 256>>>(pw1, wih);
    fold_hh_kernel<<<dim3(NE / 32, Hn / 32), dim3(32, 8)>>>(whh);
    fold_bias_kernel<<<NE / 256, 256>>>(wih, pb1, bih, bhh);
    gemm1_kernel<<<dim3(1, Bn / 64), 128>>>(obs, pw0, pb0);
    gemm2_kernel<<<dim3(NE / 128, Bn / 128), 256>>>(hprev);
    gates_kernel<<<(Bn * 128) / 256, 256>>>(hprev, hout);
    heads_kernel<<<Bn / 64, 256, 196608>>>(hout, aid, hw1, hb1, hw2, hb2, out);
}

// round 4
// speedup vs baseline: 1.0049x; 1.0049x over previous
#include <cuda_runtime.h>
#include <cstdint>
#include <math.h>

#define Bn 32768
#define Gn 2048
#define Hn 512
#define An 8
#define PH 64
#define HH 32
#define KE 576      // 64 (hid) + 512 (h_prev)
#define NE 2048     // [r_sum | z_sum | i_n | h_n]

// ---------------- device scratch (no runtime allocation allowed) ----------------
__device__ float g_Wext[KE * NE];          // 4.7 MB folded weight
__device__ float g_bias[NE];
__device__ float g_hid[Bn * PH];           // 8 MB
__device__ float g_G[(size_t)Bn * NE];     // 256 MB gate pre-activations

// ---------------- helpers ----------------
__device__ __forceinline__ uint32_t f2tf(float f) {
    uint32_t r;
    asm("cvt.rna.tf32.f32 %0, %1;" : "=r"(r) : "f"(f));
    return r;
}

__device__ __forceinline__ void mma_tf32(float* d, const uint32_t* a, const uint32_t* b) {
    asm volatile(
        "mma.sync.aligned.m16n8k8.row.col.f32.tf32.tf32.f32 "
        "{%0,%1,%2,%3},{%4,%5,%6,%7},{%8,%9},{%0,%1,%2,%3};"
        : "+f"(d[0]), "+f"(d[1]), "+f"(d[2]), "+f"(d[3])
        : "r"(a[0]), "r"(a[1]), "r"(a[2]), "r"(a[3]), "r"(b[0]), "r"(b[1]));
}

// ---------------- fold kernels (run every launch; cheap) ----------------
// W_ext[p, j] = sum_h proj_w1[p,h] * w_ih[j,h]   for p<64, j<1536 ; 0 for j>=1536
__global__ void fold_wc_kernel(const float* __restrict__ w1, const float* __restrict__ wih) {
    __shared__ float As[64][64];   // proj_w1 tile (reads are warp-uniform broadcasts)
    __shared__ float Bs[64][65];   // w_ih tile transposed: Bs[k][n]
    int t = threadIdx.x;
    int n0 = blockIdx.x * 64;
    if (n0 >= 1536) {
        for (int i = t; i < 64 * 64; i += 256) {
            int p = i >> 6, j = i & 63;
            g_Wext[p * NE + n0 + j] = 0.f;
        }
        return;
    }
    int nlane = t & 63;
    int pset = t >> 6;  // uniform per warp
    float acc[16];
#pragma unroll
    for (int i = 0; i < 16; ++i) acc[i] = 0.f;

    for (int kt = 0; kt < 512; kt += 64) {
        for (int i = t * 4; i < 64 * 64; i += 1024) {
            int p = i >> 6, c = i & 63;
            float4 v = *(const float4*)(w1 + p * 512 + kt + c);
            *(float4*)&As[p][c] = v;
        }
        for (int i = t * 4; i < 64 * 64; i += 1024) {
            int r = i >> 6, c = i & 63;
            float4 v = *(const float4*)(wih + (size_t)(n0 + r) * 512 + kt + c);
            Bs[c + 0][r] = v.x; Bs[c + 1][r] = v.y; Bs[c + 2][r] = v.z; Bs[c + 3][r] = v.w;
        }
        __syncthreads();
#pragma unroll 8
        for (int k = 0; k < 64; ++k) {
            float bv = Bs[k][nlane];
#pragma unroll
            for (int pp = 0; pp < 16; ++pp)
                acc[pp] += As[pset * 16 + pp][k] * bv;
        }
        __syncthreads();
    }
#pragma unroll
    for (int pp = 0; pp < 16; ++pp)
        g_Wext[(pset * 16 + pp) * NE + n0 + nlane] = acc[pp];
}

// W_ext[64+k, j] = w_hh[src_j, k]; zero for j in [1024,1536)
__global__ void fold_hh_kernel(const float* __restrict__ whh) {
    __shared__ float s[32][33];
    int j0 = blockIdx.x * 32;  // output column
    int k0 = blockIdx.y * 32;  // k row
    int tx = threadIdx.x, ty = threadIdx.y;
    bool zero = (j0 >= 1024 && j0 < 1536);
    int srcbase = (j0 < 1024) ? j0 : j0 - 512;
    if (!zero) {
        for (int r = ty; r < 32; r += 8)
            s[r][tx] = whh[(size_t)(srcbase + r) * 512 + k0 + tx];
        __syncthreads();
        for (int r = ty; r < 32; r += 8)
            g_Wext[(size_t)(64 + k0 + r) * NE + j0 + tx] = s[tx][r];
    } else {
        for (int r = ty; r < 32; r += 8)
            g_Wext[(size_t)(64 + k0 + r) * NE + j0 + tx] = 0.f;
    }
}

__global__ void fold_bias_kernel(const float* __restrict__ wih, const float* __restrict__ pb1,
                                 const float* __restrict__ bih, const float* __restrict__ bhh) {
    int col = blockIdx.x * 256 + threadIdx.x;
    if (col >= NE) return;
    float v;
    if (col < 1536) {
        float s = 0.f;
        for (int h = 0; h < 512; ++h) s += pb1[h] * wih[(size_t)col * 512 + h];
        float bc = bih[col] + s;
        v = (col < 1024) ? (bc + bhh[col]) : bc;
    } else {
        v = bhh[col - 512];
    }
    g_bias[col] = v;
}

// ---------------- GEMM1: hid = relu(obs @ w0 + b0)  [32768,2048]x[2048,64] ----------------
__global__ __launch_bounds__(128) void gemm1_kernel(const float* __restrict__ obs,
                                                    const float* __restrict__ w0,
                                                    const float* __restrict__ b0) {
    __shared__ uint32_t As[64][36];   // (4g+c) bank pattern -> conflict free frag loads
    __shared__ uint32_t Bs[32][72];   // (8c+g) bank pattern
    int t = threadIdx.x;
    int lane = t & 31, warp = t >> 5;
    int g = lane >> 2, c = lane & 3;
    int wm = warp >> 1, wn = warp & 1;
    int m0 = blockIdx.y * 64;

    float acc[2][4][4];
#pragma unroll
    for (int i = 0; i < 2; ++i)
#pragma unroll
        for (int j = 0; j < 4; ++j)
#pragma unroll
            for (int k = 0; k < 4; ++k) acc[i][j][k] = 0.f;

    for (int kt = 0; kt < Gn; kt += 32) {
#pragma unroll
        for (int p = 0; p < 4; ++p) {
            int row = p * 16 + (t >> 3);
            int k4 = (t & 7) * 4;
            float4 v = *(const float4*)(obs + (size_t)(m0 + row) * Gn + kt + k4);
            As[row][k4 + 0] = f2tf(v.x); As[row][k4 + 1] = f2tf(v.y);
            As[row][k4 + 2] = f2tf(v.z); As[row][k4 + 3] = f2tf(v.w);
        }
#pragma unroll
        for (int p = 0; p < 4; ++p) {
            int k = p * 8 + (t >> 4);
            int n4 = (t & 15) * 4;
            float4 v = *(const float4*)(w0 + (size_t)(kt + k) * 64 + n4);
            Bs[k][n4 + 0] = f2tf(v.x); Bs[k][n4 + 1] = f2tf(v.y);
            Bs[k][n4 + 2] = f2tf(v.z); Bs[k][n4 + 3] = f2tf(v.w);
        }
        __syncthreads();
#pragma unroll
        for (int kk = 0; kk < 4; ++kk) {
            uint32_t af[2][4], bf[4][2];
#pragma unroll
            for (int fm = 0; fm < 2; ++fm) {
                int r = wm * 32 + fm * 16;
                af[fm][0] = As[r + g][kk * 8 + c];
                af[fm][1] = As[r + g + 8][kk * 8 + c];
                af[fm][2] = As[r + g][kk * 8 + c + 4];
                af[fm][3] = As[r + g + 8][kk * 8 + c + 4];
            }
#pragma unroll
            for (int fn = 0; fn < 4; ++fn) {
                int cb = wn * 32 + fn * 8;
                bf[fn][0] = Bs[kk * 8 + c][cb + g];
                bf[fn][1] = Bs[kk * 8 + c + 4][cb + g];
            }
#pragma unroll
            for (int fm = 0; fm < 2; ++fm)
#pragma unroll
                for (int fn = 0; fn < 4; ++fn)
                    mma_tf32(acc[fm][fn], af[fm], bf[fn]);
        }
        __syncthreads();
    }
#pragma unroll
    for (int fm = 0; fm < 2; ++fm) {
        int row = m0 + wm * 32 + fm * 16 + g;
#pragma unroll
        for (int fn = 0; fn < 4; ++fn) {
            int col = wn * 32 + fn * 8 + c * 2;
            float bA = b0[col], bB = b0[col + 1];
            float2 v0 = make_float2(fmaxf(acc[fm][fn][0] + bA, 0.f), fmaxf(acc[fm][fn][1] + bB, 0.f));
            float2 v1 = make_float2(fmaxf(acc[fm][fn][2] + bA, 0.f), fmaxf(acc[fm][fn][3] + bB, 0.f));
            *(float2*)(g_hid + (size_t)row * PH + col) = v0;
            *(float2*)(g_hid + (size_t)(row + 8) * PH + col) = v1;
        }
    }
}

// ---------------- GEMM2: G = [hid | h_prev] @ W_ext + bias  M=32768 N=2048 K=576 ----------------
__global__ __launch_bounds__(256) void gemm2_kernel(const float* __restrict__ hprev) {
    __shared__ uint32_t As[128][36];
    __shared__ uint32_t Bs[32][136];
    int t = threadIdx.x;
    int lane = t & 31, warp = t >> 5;
    int g = lane >> 2, c = lane & 3;
    int wm = warp >> 2, wn = warp & 3;  // 2 x 4 warp grid, warp tile 64x32
    int m0 = blockIdx.y * 128;
    int n0 = blockIdx.x * 128;

    float acc[4][4][4];
#pragma unroll
    for (int i = 0; i < 4; ++i)
#pragma unroll
        for (int j = 0; j < 4; ++j)
#pragma unroll
            for (int k = 0; k < 4; ++k) acc[i][j][k] = 0.f;

    for (int kt = 0; kt < KE; kt += 32) {
#pragma unroll
        for (int p = 0; p < 4; ++p) {
            int row = p * 32 + (t >> 3);
            int k4 = (t & 7) * 4;
            int gk = kt + k4;
            float4 v;
            if (gk < PH)
                v = *(const float4*)(g_hid + (size_t)(m0 + row) * PH + gk);
            else
                v = *(const float4*)(hprev + (size_t)(m0 + row) * Hn + (gk - PH));
            As[row][k4 + 0] = f2tf(v.x); As[row][k4 + 1] = f2tf(v.y);
            As[row][k4 + 2] = f2tf(v.z); As[row][k4 + 3] = f2tf(v.w);
        }
#pragma unroll
        for (int p = 0; p < 4; ++p) {
            int k = p * 8 + (t >> 5);
            int nn = (t & 31) * 4;
            float4 v = *(const float4*)(g_Wext + (size_t)(kt + k) * NE + n0 + nn);
            Bs[k][nn + 0] = f2tf(v.x); Bs[k][nn + 1] = f2tf(v.y);
            Bs[k][nn + 2] = f2tf(v.z); Bs[k][nn + 3] = f2tf(v.w);
        }
        __syncthreads();
#pragma unroll
        for (int kk = 0; kk < 4; ++kk) {
            uint32_t af[4][4], bf[4][2];
#pragma unroll
            for (int fm = 0; fm < 4; ++fm) {
                int r = wm * 64 + fm * 16;
                af[fm][0] = As[r + g][kk * 8 + c];
                af[fm][1] = As[r + g + 8][kk * 8 + c];
                af[fm][2] = As[r + g][kk * 8 + c + 4];
                af[fm][3] = As[r + g + 8][kk * 8 + c + 4];
            }
#pragma unroll
            for (int fn = 0; fn < 4; ++fn) {
                int cb = wn * 32 + fn * 8;
                bf[fn][0] = Bs[kk * 8 + c][cb + g];
                bf[fn][1] = Bs[kk * 8 + c + 4][cb + g];
            }
#pragma unroll
            for (int fm = 0; fm < 4; ++fm)
#pragma unroll
                for (int fn = 0; fn < 4; ++fn)
                    mma_tf32(acc[fm][fn], af[fm], bf[fn]);
        }
        __syncthreads();
    }
#pragma unroll
    for (int fm = 0; fm < 4; ++fm) {
        int row = m0 + wm * 64 + fm * 16 + g;
#pragma unroll
        for (int fn = 0; fn < 4; ++fn) {
            int col = n0 + wn * 32 + fn * 8 + c * 2;
            float bA = g_bias[col], bB = g_bias[col + 1];
            float2 v0 = make_float2(acc[fm][fn][0] + bA, acc[fm][fn][1] + bB);
            float2 v1 = make_float2(acc[fm][fn][2] + bA, acc[fm][fn][3] + bB);
            *(float2*)(g_G + (size_t)row * NE + col) = v0;
            *(float2*)(g_G + (size_t)(row + 8) * NE + col) = v1;
        }
    }
}

// ---------------- gates: h = (1-z)*n + z*h_prev ----------------
__device__ __forceinline__ float gatef(float pr, float pz, float pin, float phn, float hp) {
    float r = 1.f / (1.f + __expf(-pr));
    float z = 1.f / (1.f + __expf(-pz));
    float n = tanhf(pin + r * phn);
    return (1.f - z) * n + z * hp;
}

__global__ __launch_bounds__(256) void gates_kernel(const float* __restrict__ hprev,
                                                    float* __restrict__ hout) {
    int i = blockIdx.x * 256 + threadIdx.x;  // Bn*128 threads
    int b = i >> 7;
    int j = (i & 127) << 2;
    const float* row = g_G + (size_t)b * NE;
    float4 xr = *(const float4*)(row + j);
    float4 xz = *(const float4*)(row + 512 + j);
    float4 xi = *(const float4*)(row + 1024 + j);
    float4 xh = *(const float4*)(row + 1536 + j);
    float4 hp = *(const float4*)(hprev + (size_t)b * Hn + j);
    float4 o;
    o.x = gatef(xr.x, xz.x, xi.x, xh.x, hp.x);
    o.y = gatef(xr.y, xz.y, xi.y, xh.y, hp.y);
    o.z = gatef(xr.z, xz.z, xi.z, xh.z, hp.z);
    o.w = gatef(xr.w, xz.w, xi.w, xh.w, hp.w);
    *(float4*)(hout + (size_t)b * Hn + j) = o;
}

// ---------------- heads: per-sample agent head, smem-staged weights ----------------
__global__ __launch_bounds__(256) void heads_kernel(const float* __restrict__ h,
                                                    const int* __restrict__ aid,
                                                    const float* __restrict__ w1,
                                                    const float* __restrict__ b1,
                                                    const float* __restrict__ w2,
                                                    const float* __restrict__ b2,
                                                    float* __restrict__ out) {
    extern __shared__ float sm[];
    float* hs = sm;                 // 64 x 512
    float* w1s = sm + 64 * Hn;      // 512 x 32
    __shared__ int s_aid[64];
    __shared__ int s_list[64];
    __shared__ int s_cnt;
    int t = threadIdx.x, lane = t & 31, warp = t >> 5;
    int b0 = blockIdx.x * 64;

    {
        const float4* src = (const float4*)(h + (size_t)b0 * Hn);
        float4* dst = (float4*)hs;
        for (int i = t; i < 64 * 128; i += 256) dst[i] = src[i];
    }
    if (t < 64) s_aid[t] = aid[b0 + t];
    __syncthreads();

    for (int a = 0; a < An; ++a) {
        if (t == 0) s_cnt = 0;
        __syncthreads();
        if (t < 64 && s_aid[t] == a) {
            int p = atomicAdd(&s_cnt, 1);
            s_list[p] = t;
        }
        __syncthreads();
        int cnt = s_cnt;
        if (cnt > 0) {
            const float4* wsrc = (const float4*)(w1 + (size_t)a * Hn * HH);
            float4* wdst = (float4*)w1s;
            for (int i = t; i < Hn * HH / 4; i += 256) wdst[i] = wsrc[i];
            __syncthreads();
            float w2v = w2[a * 32 + lane];
            float b1v = b1[a * 32 + lane];
            float b2v = b2[a];
            for (int s = warp * 2; s < cnt; s += 16) {
                int l0 = s_list[s];
                bool has1 = (s + 1 < cnt);
                int l1 = has1 ? s_list[s + 1] : l0;
                const float4* r0 = (const float4*)(hs + l0 * Hn);
                const float4* r1 = (const float4*)(hs + l1 * Hn);
                float a0 = 0.f, a1 = 0.f;
#pragma unroll 8
                for (int hq = 0; hq < 128; ++hq) {
                    float4 x0 = r0[hq];
                    float4 x1 = r1[hq];
                    float wv0 = w1s[(hq * 4 + 0) * 32 + lane];
                    float wv1 = w1s[(hq * 4 + 1) * 32 + lane];
                    float wv2 = w1s[(hq * 4 + 2) * 32 + lane];
                    float wv3 = w1s[(hq * 4 + 3) * 32 + lane];
                    a0 = fmaf(x0.x, wv0, a0); a0 = fmaf(x0.y, wv1, a0);
                    a0 = fmaf(x0.z, wv2, a0); a0 = fmaf(x0.w, wv3, a0);
                    a1 = fmaf(x1.x, wv0, a1); a1 = fmaf(x1.y, wv1, a1);
                    a1 = fmaf(x1.z, wv2, a1); a1 = fmaf(x1.w, wv3, a1);
                }
                float v0 = fmaxf(a0 + b1v, 0.f) * w2v;
                float v1 = fmaxf(a1 + b1v, 0.f) * w2v;
#pragma unroll
                for (int off = 16; off; off >>= 1) {
                    v0 += __shfl_xor_sync(0xFFFFFFFFu, v0, off);
                    v1 += __shfl_xor_sync(0xFFFFFFFFu, v1, off);
                }
                if (lane == 0) {
                    out[b0 + l0] = v0 + b2v;
                    if (has1) out[b0 + l1] = v1 + b2v;
                }
            }
            __syncthreads();
        } else {
            __syncthreads();
        }
    }
}

// ---------------- launch ----------------
extern "C" void kernel_launch(void* const* d_in, const int* in_sizes, int n_in,
                              void* d_out, int out_size) {
    const float* obs   = (const float*)d_in[0];
    const float* hprev = (const float*)d_in[1];   // [1,B,H]
    const int*   aid   = (const int*)d_in[2];
    const float* pw0   = (const float*)d_in[3];
    const float* pb0   = (const float*)d_in[4];
    const float* pw1   = (const float*)d_in[5];
    const float* pb1   = (const float*)d_in[6];
    const float* wih   = (const float*)d_in[7];
    const float* whh   = (const float*)d_in[8];
    const float* bih   = (const float*)d_in[9];
    const float* bhh   = (const float*)d_in[10];
    const float* hw1   = (const float*)d_in[11];
    const float* hb1   = (const float*)d_in[12];
    const float* hw2   = (const float*)d_in[13];
    const float* hb2   = (const float*)d_in[14];

    float* out  = (float*)d_out;
    float* hout = out + Bn;  // h_critic_next region

    cudaFuncSetAttribute(heads_kernel, cudaFuncAttributeMaxDynamicSharedMemorySize, 196608);

    fold_wc_kernel<<<NE / 64, 256>>>(pw1, wih);
    fold_hh_kernel<<<dim3(NE / 32, Hn / 32), dim3(32, 8)>>>(whh);
    fold_bias_kernel<<<NE / 256, 256>>>(wih, pb1, bih, bhh);
    gemm1_kernel<<<dim3(1, Bn / 64), 128>>>(obs, pw0, pb0);
    gemm2_kernel<<<dim3(NE / 128, Bn / 128), 256>>>(hprev);
    gates_kernel<<<(Bn * 128) / 256, 256>>>(hprev, hout);
    heads_kernel<<<Bn / 64, 256, 196608>>>(hout, aid, hw1, hb1, hw2, hb2, out);
}

// round 6
// speedup vs baseline: 1.1789x; 1.1732x over previous
#include <cuda_runtime.h>
#include <cstdint>
#include <math.h>

#define Bn 32768
#define Gn 2048
#define Hn 512
#define An 8
#define PH 64
#define HH 32
#define KE 576      // 64 (hid) + 512 (h_prev)
#define NE 2048     // interleaved: col 4j+{0,1,2,3} = {r_sum, z_sum, i_n, h_n} for h-unit j

// ---------------- device scratch ----------------
__device__ float g_Wext[KE * NE];          // 4.7 MB folded weight (interleaved cols)
__device__ float g_bias[NE];               // interleaved
__device__ float g_hid[Bn * PH];           // 8 MB

// column permutation: original col C in [0,2048) -> interleaved position
__device__ __forceinline__ int colp(int C) { return 4 * (C & 511) + (C >> 9); }

// ---------------- mma (raw fp32 bits -> HW truncates to TF32) ----------------
__device__ __forceinline__ void mma_tf32(float* d, const uint32_t* a, const uint32_t* b) {
    asm volatile(
        "mma.sync.aligned.m16n8k8.row.col.f32.tf32.tf32.f32 "
        "{%0,%1,%2,%3},{%4,%5,%6,%7},{%8,%9},{%0,%1,%2,%3};"
        : "+f"(d[0]), "+f"(d[1]), "+f"(d[2]), "+f"(d[3])
        : "r"(a[0]), "r"(a[1]), "r"(a[2]), "r"(a[3]), "r"(b[0]), "r"(b[1]));
}

// ---------------- cp.async helpers ----------------
__device__ __forceinline__ void cpa16(uint32_t s, const void* g) {
    asm volatile("cp.async.cg.shared.global [%0], [%1], 16;" :: "r"(s), "l"(g));
}
#define CP_COMMIT asm volatile("cp.async.commit_group;")
#define CP_WAIT(n) asm volatile("cp.async.wait_group %0;" :: "n"(n))

// ---------------- fold kernels ----------------
// W_ext[p, colp(C)] = sum_h proj_w1[p,h] * w_ih[C,h]  for C<1536 ; 0 for C>=1536
__global__ void fold_wc_kernel(const float* __restrict__ w1, const float* __restrict__ wih) {
    __shared__ float As[64][64];
    __shared__ float Bs[64][65];
    int t = threadIdx.x;
    int n0 = blockIdx.x * 64;
    if (n0 >= 1536) {
        for (int i = t; i < 64 * 64; i += 256) {
            int p = i >> 6, j = i & 63;
            g_Wext[p * NE + colp(n0 + j)] = 0.f;
        }
        return;
    }
    int nlane = t & 63;
    int pset = t >> 6;
    float acc[16];
#pragma unroll
    for (int i = 0; i < 16; ++i) acc[i] = 0.f;

    for (int kt = 0; kt < 512; kt += 64) {
        for (int i = t * 4; i < 64 * 64; i += 1024) {
            int p = i >> 6, c = i & 63;
            float4 v = *(const float4*)(w1 + p * 512 + kt + c);
            *(float4*)&As[p][c] = v;
        }
        for (int i = t * 4; i < 64 * 64; i += 1024) {
            int r = i >> 6, c = i & 63;
            float4 v = *(const float4*)(wih + (size_t)(n0 + r) * 512 + kt + c);
            Bs[c + 0][r] = v.x; Bs[c + 1][r] = v.y; Bs[c + 2][r] = v.z; Bs[c + 3][r] = v.w;
        }
        __syncthreads();
#pragma unroll 8
        for (int k = 0; k < 64; ++k) {
            float bv = Bs[k][nlane];
#pragma unroll
            for (int pp = 0; pp < 16; ++pp)
                acc[pp] += As[pset * 16 + pp][k] * bv;
        }
        __syncthreads();
    }
    int cp_ = colp(n0 + nlane);
#pragma unroll
    for (int pp = 0; pp < 16; ++pp)
        g_Wext[(pset * 16 + pp) * NE + cp_] = acc[pp];
}

// W_ext[64+k, colp(C)]: C<1024 -> whh[C,k]; [1024,1536) -> 0; >=1536 -> whh[C-512,k]
__global__ void fold_hh_kernel(const float* __restrict__ whh) {
    __shared__ float s[32][33];
    int j0 = blockIdx.x * 32;
    int k0 = blockIdx.y * 32;
    int tx = threadIdx.x, ty = threadIdx.y;
    int C = j0 + tx;
    bool zero = (j0 >= 1024 && j0 < 1536);
    int srcbase = (j0 < 1024) ? j0 : j0 - 512;
    int cp_ = colp(C);
    if (!zero) {
        for (int r = ty; r < 32; r += 8)
            s[r][tx] = whh[(size_t)(srcbase + r) * 512 + k0 + tx];
        __syncthreads();
        for (int r = ty; r < 32; r += 8)
            g_Wext[(size_t)(64 + k0 + r) * NE + cp_] = s[tx][r];
    } else {
        for (int r = ty; r < 32; r += 8)
            g_Wext[(size_t)(64 + k0 + r) * NE + cp_] = 0.f;
    }
}

// warp-parallel bias fold
__global__ __launch_bounds__(256) void fold_bias_kernel(const float* __restrict__ wih,
                                                        const float* __restrict__ pb1,
                                                        const float* __restrict__ bih,
                                                        const float* __restrict__ bhh) {
    int C = (blockIdx.x * 256 + threadIdx.x) >> 5;
    int lane = threadIdx.x & 31;
    if (C >= NE) return;
    float v;
    if (C < 1536) {
        float s = 0.f;
        for (int h = lane; h < 512; h += 32) s += pb1[h] * wih[(size_t)C * 512 + h];
#pragma unroll
        for (int off = 16; off; off >>= 1) s += __shfl_xor_sync(0xFFFFFFFFu, s, off);
        float bc = bih[C] + s;
        v = (C < 1024) ? (bc + bhh[C]) : bc;
    } else {
        v = bhh[C - 512];
    }
    if (lane == 0) g_bias[colp(C)] = v;
}

// ---------------- GEMM1: hid = relu(obs @ w0 + b0), cp.async double-buffered ----------------
__global__ __launch_bounds__(128) void gemm1_kernel(const float* __restrict__ obs,
                                                    const float* __restrict__ w0,
                                                    const float* __restrict__ b0) {
    __shared__ uint32_t As[2][64][36];
    __shared__ uint32_t Bs[2][32][72];
    int t = threadIdx.x;
    int lane = t & 31, warp = t >> 5;
    int g = lane >> 2, c = lane & 3;
    int wm = warp >> 1, wn = warp & 1;
    int m0 = blockIdx.y * 64;

    float acc[2][4][4];
#pragma unroll
    for (int i = 0; i < 2; ++i)
#pragma unroll
        for (int j = 0; j < 4; ++j)
#pragma unroll
            for (int k = 0; k < 4; ++k) acc[i][j][k] = 0.f;

    int arow = t >> 3, ak4 = (t & 7) * 4;
    int bk = t >> 4, bn4 = (t & 15) * 4;

    auto load_tiles = [&](int kt, int buf) {
#pragma unroll
        for (int p = 0; p < 4; ++p) {
            int row = p * 16 + arow;
            cpa16((uint32_t)__cvta_generic_to_shared(&As[buf][row][ak4]),
                  obs + (size_t)(m0 + row) * Gn + kt + ak4);
        }
#pragma unroll
        for (int p = 0; p < 4; ++p) {
            int k = p * 8 + bk;
            cpa16((uint32_t)__cvta_generic_to_shared(&Bs[buf][k][bn4]),
                  w0 + (size_t)(kt + k) * 64 + bn4);
        }
    };

    const int NSTEP = Gn / 32;  // 64
    load_tiles(0, 0);
    CP_COMMIT;

    for (int i = 0; i < NSTEP; ++i) {
        if (i + 1 < NSTEP) {
            load_tiles((i + 1) * 32, (i + 1) & 1);
            CP_COMMIT;
            CP_WAIT(1);
        } else {
            CP_WAIT(0);
        }
        __syncthreads();
        int buf = i & 1;
#pragma unroll
        for (int kk = 0; kk < 4; ++kk) {
            uint32_t af[2][4], bf[4][2];
#pragma unroll
            for (int fm = 0; fm < 2; ++fm) {
                int r = wm * 32 + fm * 16;
                af[fm][0] = As[buf][r + g][kk * 8 + c];
                af[fm][1] = As[buf][r + g + 8][kk * 8 + c];
                af[fm][2] = As[buf][r + g][kk * 8 + c + 4];
                af[fm][3] = As[buf][r + g + 8][kk * 8 + c + 4];
            }
#pragma unroll
            for (int fn = 0; fn < 4; ++fn) {
                int cb = wn * 32 + fn * 8;
                bf[fn][0] = Bs[buf][kk * 8 + c][cb + g];
                bf[fn][1] = Bs[buf][kk * 8 + c + 4][cb + g];
            }
#pragma unroll
            for (int fm = 0; fm < 2; ++fm)
#pragma unroll
                for (int fn = 0; fn < 4; ++fn)
                    mma_tf32(acc[fm][fn], af[fm], bf[fn]);
        }
        __syncthreads();
    }
#pragma unroll
    for (int fm = 0; fm < 2; ++fm) {
        int row = m0 + wm * 32 + fm * 16 + g;
#pragma unroll
        for (int fn = 0; fn < 4; ++fn) {
            int col = wn * 32 + fn * 8 + c * 2;
            float bA = b0[col], bB = b0[col + 1];
            float2 v0 = make_float2(fmaxf(acc[fm][fn][0] + bA, 0.f), fmaxf(acc[fm][fn][1] + bB, 0.f));
            float2 v1 = make_float2(fmaxf(acc[fm][fn][2] + bA, 0.f), fmaxf(acc[fm][fn][3] + bB, 0.f));
            *(float2*)(g_hid + (size_t)row * PH + col) = v0;
            *(float2*)(g_hid + (size_t)(row + 8) * PH + col) = v1;
        }
    }
}

// ---------------- GEMM2 + fused GRU gates ----------------
// G = [hid | h_prev] @ W_ext + bias (interleaved cols), then h = (1-z)*n + z*h_prev
// dynamic smem: As[2][128][36] (36864B) | Bs[2][32][136] (34816B); epilogue aliases as [128][132] floats
#define G2_AS_BYTES (128 * 36 * 4)
#define G2_BS_BYTES (32 * 136 * 4)
#define G2_SMEM (2 * G2_AS_BYTES + 2 * G2_BS_BYTES)  // 71680

__global__ __launch_bounds__(256) void gemm2_kernel(const float* __restrict__ hprev,
                                                    float* __restrict__ hout) {
    extern __shared__ char smraw[];
    uint32_t* As[2] = {(uint32_t*)smraw, (uint32_t*)(smraw + G2_AS_BYTES)};
    uint32_t* Bs[2] = {(uint32_t*)(smraw + 2 * G2_AS_BYTES),
                       (uint32_t*)(smraw + 2 * G2_AS_BYTES + G2_BS_BYTES)};
    int t = threadIdx.x;
    int lane = t & 31, warp = t >> 5;
    int g = lane >> 2, c = lane & 3;
    int wm = warp >> 2, wn = warp & 3;  // 2 x 4 warps, warp tile 64x32
    int m0 = blockIdx.y * 128;
    int n0 = blockIdx.x * 128;

    float acc[4][4][4];
#pragma unroll
    for (int i = 0; i < 4; ++i)
#pragma unroll
        for (int j = 0; j < 4; ++j)
#pragma unroll
            for (int k = 0; k < 4; ++k) acc[i][j][k] = 0.f;

    int arow = t >> 3, ak4 = (t & 7) * 4;
    int bk = t >> 5, bnn = (t & 31) * 4;

    auto load_tiles = [&](int kt, int buf) {
#pragma unroll
        for (int p = 0; p < 4; ++p) {
            int row = p * 32 + arow;
            int gk = kt + ak4;
            const float* src = (gk < PH)
                ? (g_hid + (size_t)(m0 + row) * PH + gk)
                : (hprev + (size_t)(m0 + row) * Hn + (gk - PH));
            cpa16((uint32_t)__cvta_generic_to_shared(&As[buf][row * 36 + ak4]), src);
        }
#pragma unroll
        for (int p = 0; p < 4; ++p) {
            int k = p * 8 + bk;
            cpa16((uint32_t)__cvta_generic_to_shared(&Bs[buf][k * 136 + bnn]),
                  g_Wext + (size_t)(kt + k) * NE + n0 + bnn);
        }
    };

    const int NSTEP = KE / 32;  // 18
    load_tiles(0, 0);
    CP_COMMIT;

    for (int i = 0; i < NSTEP; ++i) {
        if (i + 1 < NSTEP) {
            load_tiles((i + 1) * 32, (i + 1) & 1);
            CP_COMMIT;
            CP_WAIT(1);
        } else {
            CP_WAIT(0);
        }
        __syncthreads();
        const uint32_t* A = As[i & 1];
        const uint32_t* B = Bs[i & 1];
#pragma unroll
        for (int kk = 0; kk < 4; ++kk) {
            uint32_t af[4][4], bf[4][2];
#pragma unroll
            for (int fm = 0; fm < 4; ++fm) {
                int r = wm * 64 + fm * 16;
                af[fm][0] = A[(r + g) * 36 + kk * 8 + c];
                af[fm][1] = A[(r + g + 8) * 36 + kk * 8 + c];
                af[fm][2] = A[(r + g) * 36 + kk * 8 + c + 4];
                af[fm][3] = A[(r + g + 8) * 36 + kk * 8 + c + 4];
            }
#pragma unroll
            for (int fn = 0; fn < 4; ++fn) {
                int cb = wn * 32 + fn * 8;
                bf[fn][0] = B[(kk * 8 + c) * 136 + cb + g];
                bf[fn][1] = B[(kk * 8 + c + 4) * 136 + cb + g];
            }
#pragma unroll
            for (int fm = 0; fm < 4; ++fm)
#pragma unroll
                for (int fn = 0; fn < 4; ++fn)
                    mma_tf32(acc[fm][fn], af[fm], bf[fn]);
        }
        __syncthreads();
    }

    // ---- fused gate epilogue: stage acc -> smem, compute h directly ----
    float* epi = (float*)smraw;  // [128][132]
#pragma unroll
    for (int fm = 0; fm < 4; ++fm) {
        int r0 = wm * 64 + fm * 16 + g;
#pragma unroll
        for (int fn = 0; fn < 4; ++fn) {
            int cc = wn * 32 + fn * 8 + 2 * c;
            epi[r0 * 132 + cc]           = acc[fm][fn][0];
            epi[r0 * 132 + cc + 1]       = acc[fm][fn][1];
            epi[(r0 + 8) * 132 + cc]     = acc[fm][fn][2];
            epi[(r0 + 8) * 132 + cc + 1] = acc[fm][fn][3];
        }
    }
    __syncthreads();
    int hbase = n0 >> 2;  // 32 h-columns per block
#pragma unroll
    for (int q = 0; q < 16; ++q) {
        int i = q * 256 + t;
        int row = i >> 5, jj = i & 31;
        float4 gq = *(float4*)&epi[row * 132 + 4 * jj];
        float4 bq = *(const float4*)(g_bias + n0 + 4 * jj);
        size_t idx = (size_t)(m0 + row) * Hn + hbase + jj;
        float hp = hprev[idx];
        float r = 1.f / (1.f + __expf(-(gq.x + bq.x)));
        float z = 1.f / (1.f + __expf(-(gq.y + bq.y)));
        float n = tanhf(gq.z + bq.z + r * (gq.w + bq.w));
        hout[idx] = (1.f - z) * n + z * hp;
    }
}

// ---------------- heads: per-sample agent head, smem-staged weights ----------------
__global__ __launch_bounds__(256) void heads_kernel(const float* __restrict__ h,
                                                    const int* __restrict__ aid,
                                                    const float* __restrict__ w1,
                                                    const float* __restrict__ b1,
                                                    const float* __restrict__ w2,
                                                    const float* __restrict__ b2,
                                                    float* __restrict__ out) {
    extern __shared__ float sm[];
    float* hs = sm;                 // 64 x 512
    float* w1s = sm + 64 * Hn;      // 512 x 32
    __shared__ int s_aid[64];
    __shared__ int s_list[64];
    __shared__ int s_cnt;
    int t = threadIdx.x, lane = t & 31, warp = t >> 5;
    int b0 = blockIdx.x * 64;

    {
        const float4* src = (const float4*)(h + (size_t)b0 * Hn);
        float4* dst = (float4*)hs;
        for (int i = t; i < 64 * 128; i += 256) dst[i] = src[i];
    }
    if (t < 64) s_aid[t] = aid[b0 + t];
    __syncthreads();

    for (int a = 0; a < An; ++a) {
        if (t == 0) s_cnt = 0;
        __syncthreads();
        if (t < 64 && s_aid[t] == a) {
            int p = atomicAdd(&s_cnt, 1);
            s_list[p] = t;
        }
        __syncthreads();
        int cnt = s_cnt;
        if (cnt > 0) {
            const float4* wsrc = (const float4*)(w1 + (size_t)a * Hn * HH);
            float4* wdst = (float4*)w1s;
            for (int i = t; i < Hn * HH / 4; i += 256) wdst[i] = wsrc[i];
            __syncthreads();
            float w2v = w2[a * 32 + lane];
            float b1v = b1[a * 32 + lane];
            float b2v = b2[a];
            for (int s = warp * 2; s < cnt; s += 16) {
                int l0 = s_list[s];
                bool has1 = (s + 1 < cnt);
                int l1 = has1 ? s_list[s + 1] : l0;
                const float4* r0 = (const float4*)(hs + l0 * Hn);
                const float4* r1 = (const float4*)(hs + l1 * Hn);
                float a0 = 0.f, a1 = 0.f;
#pragma unroll 8
                for (int hq = 0; hq < 128; ++hq) {
                    float4 x0 = r0[hq];
                    float4 x1 = r1[hq];
                    float wv0 = w1s[(hq * 4 + 0) * 32 + lane];
                    float wv1 = w1s[(hq * 4 + 1) * 32 + lane];
                    float wv2 = w1s[(hq * 4 + 2) * 32 + lane];
                    float wv3 = w1s[(hq * 4 + 3) * 32 + lane];
                    a0 = fmaf(x0.x, wv0, a0); a0 = fmaf(x0.y, wv1, a0);
                    a0 = fmaf(x0.z, wv2, a0); a0 = fmaf(x0.w, wv3, a0);
                    a1 = fmaf(x1.x, wv0, a1); a1 = fmaf(x1.y, wv1, a1);
                    a1 = fmaf(x1.z, wv2, a1); a1 = fmaf(x1.w, wv3, a1);
                }
                float v0 = fmaxf(a0 + b1v, 0.f) * w2v;
                float v1 = fmaxf(a1 + b1v, 0.f) * w2v;
#pragma unroll
                for (int off = 16; off; off >>= 1) {
                    v0 += __shfl_xor_sync(0xFFFFFFFFu, v0, off);
                    v1 += __shfl_xor_sync(0xFFFFFFFFu, v1, off);
                }
                if (lane == 0) {
                    out[b0 + l0] = v0 + b2v;
                    if (has1) out[b0 + l1] = v1 + b2v;
                }
            }
            __syncthreads();
        } else {
            __syncthreads();
        }
    }
}

// ---------------- launch ----------------
extern "C" void kernel_launch(void* const* d_in, const int* in_sizes, int n_in,
                              void* d_out, int out_size) {
    const float* obs   = (const float*)d_in[0];
    const float* hprev = (const float*)d_in[1];
    const int*   aid   = (const int*)d_in[2];
    const float* pw0   = (const float*)d_in[3];
    const float* pb0   = (const float*)d_in[4];
    const float* pw1   = (const float*)d_in[5];
    const float* pb1   = (const float*)d_in[6];
    const float* wih   = (const float*)d_in[7];
    const float* whh   = (const float*)d_in[8];
    const float* bih   = (const float*)d_in[9];
    const float* bhh   = (const float*)d_in[10];
    const float* hw1   = (const float*)d_in[11];
    const float* hb1   = (const float*)d_in[12];
    const float* hw2   = (const float*)d_in[13];
    const float* hb2   = (const float*)d_in[14];

    float* out  = (float*)d_out;
    float* hout = out + Bn;

    cudaFuncSetAttribute(heads_kernel, cudaFuncAttributeMaxDynamicSharedMemorySize, 196608);
    cudaFuncSetAttribute(gemm2_kernel, cudaFuncAttributeMaxDynamicSharedMemorySize, G2_SMEM);

    fold_wc_kernel<<<NE / 64, 256>>>(pw1, wih);
    fold_hh_kernel<<<dim3(NE / 32, Hn / 32), dim3(32, 8)>>>(whh);
    fold_bias_kernel<<<NE * 32 / 256, 256>>>(wih, pb1, bih, bhh);
    gemm1_kernel<<<dim3(1, Bn / 64), 128>>>(obs, pw0, pb0);
    gemm2_kernel<<<dim3(NE / 128, Bn / 128), 256, G2_SMEM>>>(hprev, hout);
    heads_kernel<<<Bn / 64, 256, 196608>>>(hout, aid, hw1, hb1, hw2, hb2, out);
}

// round 12
// speedup vs baseline: 1.6403x; 1.3913x over previous
#include <cuda_runtime.h>
#include <cuda_bf16.h>
#include <cstdint>
#include <math.h>

#define Bn 32768
#define Gn 2048
#define Hn 512
#define An 8
#define PH 64
#define HH 32
#define KE 576      // 64 (hid) + 512 (h_prev)
#define NE 2048     // interleaved: col 4j+{0,1,2,3} = {r_sum, z_sum, i_n, h_n}

// ---------------- device scratch ----------------
__device__ __nv_bfloat16 g_WextT[(size_t)NE * KE];  // folded weight, [n][k] bf16
__device__ float g_bias[NE];                        // interleaved fp32
__device__ __nv_bfloat16 g_hid[(size_t)Bn * PH];    // gemm1 output, bf16
__device__ __nv_bfloat16 g_hprev_b[(size_t)Bn * Hn]; // bf16 copy of h_prev

__device__ __forceinline__ int colp(int C) { return 4 * (C & 511) + (C >> 9); }

__device__ __forceinline__ uint32_t packbf(float a, float b) {
    __nv_bfloat162 v = __float22bfloat162_rn(make_float2(a, b));
    return *(uint32_t*)&v;
}

// ---------------- mma ----------------
__device__ __forceinline__ void mma_tf32(float* d, const uint32_t* a, const uint32_t* b) {
    asm volatile(
        "mma.sync.aligned.m16n8k8.row.col.f32.tf32.tf32.f32 "
        "{%0,%1,%2,%3},{%4,%5,%6,%7},{%8,%9},{%0,%1,%2,%3};"
        : "+f"(d[0]), "+f"(d[1]), "+f"(d[2]), "+f"(d[3])
        : "r"(a[0]), "r"(a[1]), "r"(a[2]), "r"(a[3]), "r"(b[0]), "r"(b[1]));
}
__device__ __forceinline__ void mma_bf16(float* d, const uint32_t* a, const uint32_t* b) {
    asm volatile(
        "mma.sync.aligned.m16n8k16.row.col.f32.bf16.bf16.f32 "
        "{%0,%1,%2,%3},{%4,%5,%6,%7},{%8,%9},{%0,%1,%2,%3};"
        : "+f"(d[0]), "+f"(d[1]), "+f"(d[2]), "+f"(d[3])
        : "r"(a[0]), "r"(a[1]), "r"(a[2]), "r"(a[3]), "r"(b[0]), "r"(b[1]));
}

// ---------------- cp.async ----------------
__device__ __forceinline__ uint32_t smem_u32(const void* p) {
    return (uint32_t)__cvta_generic_to_shared(p);
}
__device__ __forceinline__ void cpa16(uint32_t s, const void* g) {
    asm volatile("cp.async.cg.shared.global [%0], [%1], 16;" :: "r"(s), "l"(g));
}
#define CP_COMMIT asm volatile("cp.async.commit_group;")
#define CP_WAIT(n) asm volatile("cp.async.wait_group %0;" :: "n"(n))

// ---------------- fold kernels ----------------
// g_WextT[colp(C)][p] = dot(proj_w1[p,:], w_ih[C,:]) for C<1536, p<64; zero k<64 for C>=1536
__global__ void fold_wc_kernel(const float* __restrict__ w1, const float* __restrict__ wih) {
    __shared__ float As[64][64];
    __shared__ float Bs[64][65];
    int t = threadIdx.x;
    int n0 = blockIdx.x * 64;
    if (n0 >= 1536) {
        for (int i = t; i < 64 * 64; i += 256) {
            int p = i & 63, j = i >> 6;
            g_WextT[(size_t)colp(n0 + j) * KE + p] = __float2bfloat16(0.f);
        }
        return;
    }
    int nlane = t & 63;
    int pset = t >> 6;
    float acc[16];
#pragma unroll
    for (int i = 0; i < 16; ++i) acc[i] = 0.f;

    for (int kt = 0; kt < 512; kt += 64) {
        for (int i = t * 4; i < 64 * 64; i += 1024) {
            int p = i >> 6, c = i & 63;
            *(float4*)&As[p][c] = *(const float4*)(w1 + p * 512 + kt + c);
        }
        for (int i = t * 4; i < 64 * 64; i += 1024) {
            int r = i >> 6, c = i & 63;
            float4 v = *(const float4*)(wih + (size_t)(n0 + r) * 512 + kt + c);
            Bs[c + 0][r] = v.x; Bs[c + 1][r] = v.y; Bs[c + 2][r] = v.z; Bs[c + 3][r] = v.w;
        }
        __syncthreads();
#pragma unroll 8
        for (int k = 0; k < 64; ++k) {
            float bv = Bs[k][nlane];
#pragma unroll
            for (int pp = 0; pp < 16; ++pp)
                acc[pp] += As[pset * 16 + pp][k] * bv;
        }
        __syncthreads();
    }
    uint32_t* dst = (uint32_t*)(g_WextT + (size_t)colp(n0 + nlane) * KE + pset * 16);
#pragma unroll
    for (int pp = 0; pp < 8; ++pp) dst[pp] = packbf(acc[2 * pp], acc[2 * pp + 1]);
}

// g_WextT[colp(C)][64+k]: bf16 copy of whh rows (zero for i_n block)
__global__ __launch_bounds__(256) void fold_hh_kernel(const float* __restrict__ whh) {
    int w = (blockIdx.x * 256 + threadIdx.x) >> 5;  // C in [0,2048)
    int lane = threadIdx.x & 31;
    if (w >= NE) return;
    uint2* dst = (uint2*)(g_WextT + (size_t)colp(w) * KE + 64);
    if (w >= 1024 && w < 1536) {
        uint2 z = make_uint2(0u, 0u);
        for (int i = lane; i < 128; i += 32) dst[i] = z;
    } else {
        const float4* src = (const float4*)(whh + (size_t)((w < 1024) ? w : w - 512) * 512);
        for (int i = lane; i < 128; i += 32) {
            float4 v = src[i];
            dst[i] = make_uint2(packbf(v.x, v.y), packbf(v.z, v.w));
        }
    }
}

__global__ __launch_bounds__(256) void fold_bias_kernel(const float* __restrict__ wih,
                                                        const float* __restrict__ pb1,
                                                        const float* __restrict__ bih,
                                                        const float* __restrict__ bhh) {
    int C = (blockIdx.x * 256 + threadIdx.x) >> 5;
    int lane = threadIdx.x & 31;
    if (C >= NE) return;
    float v;
    if (C < 1536) {
        float s = 0.f;
        for (int h = lane; h < 512; h += 32) s += pb1[h] * wih[(size_t)C * 512 + h];
#pragma unroll
        for (int off = 16; off; off >>= 1) s += __shfl_xor_sync(0xFFFFFFFFu, s, off);
        float bc = bih[C] + s;
        v = (C < 1024) ? (bc + bhh[C]) : bc;
    } else {
        v = bhh[C - 512];
    }
    if (lane == 0) g_bias[colp(C)] = v;
}

// ---------------- hprev -> bf16 ----------------
__global__ __launch_bounds__(256) void conv_h_kernel(const float* __restrict__ hp) {
    int i = blockIdx.x * 256 + threadIdx.x;  // each handles 8 floats
    const float4* s = (const float4*)hp;
    float4 a = s[2 * i], b = s[2 * i + 1];
    uint4 o = make_uint4(packbf(a.x, a.y), packbf(a.z, a.w), packbf(b.x, b.y), packbf(b.z, b.w));
    ((uint4*)g_hprev_b)[i] = o;
}

// ---------------- GEMM1: hid = relu(obs @ w0 + b0), tf32, bf16 output ----------------
__global__ __launch_bounds__(128) void gemm1_kernel(const float* __restrict__ obs,
                                                    const float* __restrict__ w0,
                                                    const float* __restrict__ b0) {
    __shared__ uint32_t As[2][64][36];
    __shared__ uint32_t Bs[2][32][72];
    int t = threadIdx.x;
    int lane = t & 31, warp = t >> 5;
    int g = lane >> 2, c = lane & 3;
    int wm = warp >> 1, wn = warp & 1;
    int m0 = blockIdx.y * 64;

    float acc[2][4][4];
#pragma unroll
    for (int i = 0; i < 2; ++i)
#pragma unroll
        for (int j = 0; j < 4; ++j)
#pragma unroll
            for (int k = 0; k < 4; ++k) acc[i][j][k] = 0.f;

    int arow = t >> 3, ak4 = (t & 7) * 4;
    int bk = t >> 4, bn4 = (t & 15) * 4;

    auto load_tiles = [&](int kt, int buf) {
#pragma unroll
        for (int p = 0; p < 4; ++p) {
            int row = p * 16 + arow;
            cpa16(smem_u32(&As[buf][row][ak4]), obs + (size_t)(m0 + row) * Gn + kt + ak4);
        }
#pragma unroll
        for (int p = 0; p < 4; ++p) {
            int k = p * 8 + bk;
            cpa16(smem_u32(&Bs[buf][k][bn4]), w0 + (size_t)(kt + k) * 64 + bn4);
        }
    };

    const int NSTEP = Gn / 32;
    load_tiles(0, 0);
    CP_COMMIT;

    for (int i = 0; i < NSTEP; ++i) {
        if (i + 1 < NSTEP) {
            load_tiles((i + 1) * 32, (i + 1) & 1);
            CP_COMMIT;
            CP_WAIT(1);
        } else {
            CP_WAIT(0);
        }
        __syncthreads();
        int buf = i & 1;
#pragma unroll
        for (int kk = 0; kk < 4; ++kk) {
            uint32_t af[2][4], bf[4][2];
#pragma unroll
            for (int fm = 0; fm < 2; ++fm) {
                int r = wm * 32 + fm * 16;
                af[fm][0] = As[buf][r + g][kk * 8 + c];
                af[fm][1] = As[buf][r + g + 8][kk * 8 + c];
                af[fm][2] = As[buf][r + g][kk * 8 + c + 4];
                af[fm][3] = As[buf][r + g + 8][kk * 8 + c + 4];
            }
#pragma unroll
            for (int fn = 0; fn < 4; ++fn) {
                int cb = wn * 32 + fn * 8;
                bf[fn][0] = Bs[buf][kk * 8 + c][cb + g];
                bf[fn][1] = Bs[buf][kk * 8 + c + 4][cb + g];
            }
#pragma unroll
            for (int fm = 0; fm < 2; ++fm)
#pragma unroll
                for (int fn = 0; fn < 4; ++fn)
                    mma_tf32(acc[fm][fn], af[fm], bf[fn]);
        }
        __syncthreads();
    }
    uint32_t* hb = (uint32_t*)g_hid;
#pragma unroll
    for (int fm = 0; fm < 2; ++fm) {
        int row = m0 + wm * 32 + fm * 16 + g;
#pragma unroll
        for (int fn = 0; fn < 4; ++fn) {
            int col = wn * 32 + fn * 8 + c * 2;
            float bA = b0[col], bB = b0[col + 1];
            hb[((size_t)row * PH + col) >> 1] =
                packbf(fmaxf(acc[fm][fn][0] + bA, 0.f), fmaxf(acc[fm][fn][1] + bB, 0.f));
            hb[((size_t)(row + 8) * PH + col) >> 1] =
                packbf(fmaxf(acc[fm][fn][2] + bA, 0.f), fmaxf(acc[fm][fn][3] + bB, 0.f));
        }
    }
}

// ---------------- GEMM2 bf16 + fused GRU gates ----------------
// tile 128x128, 8 warps (2x4), warp tile 64x32, K-chunk 64 (4 ksteps of K16), 9 chunks
// smem: As[2][128][36] u32-pairs | Bs[2][128][36]; epilogue aliases [128][132] fp32
#define G2_BUF 18432
#define G2_SMEM (4 * G2_BUF)  // 73728

__global__ __launch_bounds__(256) void gemm2_bf_kernel(const float* __restrict__ hprev,
                                                       float* __restrict__ hout) {
    extern __shared__ char smraw[];
    uint32_t sb = smem_u32(smraw);
    int t = threadIdx.x;
    int lane = t & 31, warp = t >> 5;
    int g = lane >> 2, cc4 = lane & 3;
    int wm = warp >> 2, wn = warp & 3;
    int m0 = blockIdx.y * 128;
    int n0 = blockIdx.x * 128;

    float acc[4][4][4];
#pragma unroll
    for (int i = 0; i < 4; ++i)
#pragma unroll
        for (int j = 0; j < 4; ++j)
#pragma unroll
            for (int k = 0; k < 4; ++k) acc[i][j][k] = 0.f;

    // chunk c: c==0 -> g_hid (k 0-63), c>=1 -> g_hprev_b (k 64+)
    auto load_chunk = [&](int c, int buf) {
        const char* abase = (c == 0)
            ? (const char*)(g_hid + (size_t)m0 * PH)
            : (const char*)(g_hprev_b + (size_t)m0 * Hn + (c - 1) * 64);
        size_t apitch = (c == 0) ? (PH * 2) : (Hn * 2);
#pragma unroll
        for (int i = 0; i < 4; ++i) {
            int id = i * 256 + t;
            int r = id >> 3, s = id & 7;
            cpa16(sb + buf * G2_BUF + r * 144 + s * 16, abase + (size_t)r * apitch + s * 16);
        }
        const char* bbase = (const char*)(g_WextT + (size_t)n0 * KE + c * 64);
#pragma unroll
        for (int i = 0; i < 4; ++i) {
            int id = i * 256 + t;
            int r = id >> 3, s = id & 7;
            cpa16(sb + 2 * G2_BUF + buf * G2_BUF + r * 144 + s * 16,
                  bbase + (size_t)r * (KE * 2) + s * 16);
        }
    };

    const int NC = KE / 64;  // 9
    load_chunk(0, 0);
    CP_COMMIT;

    for (int c = 0; c < NC; ++c) {
        if (c + 1 < NC) {
            load_chunk(c + 1, (c + 1) & 1);
            CP_COMMIT;
            CP_WAIT(1);
        } else {
            CP_WAIT(0);
        }
        __syncthreads();
        const uint32_t* A = (const uint32_t*)(smraw + (c & 1) * G2_BUF);
        const uint32_t* B = (const uint32_t*)(smraw + 2 * G2_BUF + (c & 1) * G2_BUF);
#pragma unroll
        for (int ks = 0; ks < 4; ++ks) {
            uint32_t af[4][4], bf_[4][2];
#pragma unroll
            for (int fm = 0; fm < 4; ++fm) {
                int r = wm * 64 + fm * 16;
                af[fm][0] = A[(r + g) * 36 + ks * 8 + cc4];
                af[fm][1] = A[(r + g + 8) * 36 + ks * 8 + cc4];
                af[fm][2] = A[(r + g) * 36 + ks * 8 + cc4 + 4];
                af[fm][3] = A[(r + g + 8) * 36 + ks * 8 + cc4 + 4];
            }
#pragma unroll
            for (int fn = 0; fn < 4; ++fn) {
                int nr = wn * 32 + fn * 8 + g;
                bf_[fn][0] = B[nr * 36 + ks * 8 + cc4];
                bf_[fn][1] = B[nr * 36 + ks * 8 + cc4 + 4];
            }
#pragma unroll
            for (int fm = 0; fm < 4; ++fm)
#pragma unroll
                for (int fn = 0; fn < 4; ++fn)
                    mma_bf16(acc[fm][fn], af[fm], bf_[fn]);
        }
        __syncthreads();
    }

    // ---- fused gate epilogue (validated in R6 pass) ----
    float* epi = (float*)smraw;  // [128][132]
#pragma unroll
    for (int fm = 0; fm < 4; ++fm) {
        int r0 = wm * 64 + fm * 16 + g;
#pragma unroll
        for (int fn = 0; fn < 4; ++fn) {
            int cw = wn * 32 + fn * 8 + 2 * cc4;
            epi[r0 * 132 + cw]           = acc[fm][fn][0];
            epi[r0 * 132 + cw + 1]       = acc[fm][fn][1];
            epi[(r0 + 8) * 132 + cw]     = acc[fm][fn][2];
            epi[(r0 + 8) * 132 + cw + 1] = acc[fm][fn][3];
        }
    }
    __syncthreads();
    int hbase = n0 >> 2;  // 32 h-columns per block
#pragma unroll
    for (int q = 0; q < 16; ++q) {
        int i = q * 256 + t;
        int row = i >> 5, jj = i & 31;
        float4 gq = *(float4*)&epi[row * 132 + 4 * jj];
        float4 bq = *(const float4*)(g_bias + n0 + 4 * jj);
        size_t idx = (size_t)(m0 + row) * Hn + hbase + jj;
        float hp = hprev[idx];
        float r = 1.f / (1.f + __expf(-(gq.x + bq.x)));
        float z = 1.f / (1.f + __expf(-(gq.y + bq.y)));
        float n = tanhf(gq.z + bq.z + r * (gq.w + bq.w));
        hout[idx] = (1.f - z) * n + z * hp;
    }
}

// ---------------- heads ----------------
__global__ __launch_bounds__(256) void heads_kernel(const float* __restrict__ h,
                                                    const int* __restrict__ aid,
                                                    const float* __restrict__ w1,
                                                    const float* __restrict__ b1,
                                                    const float* __restrict__ w2,
                                                    const float* __restrict__ b2,
                                                    float* __restrict__ out) {
    extern __shared__ float sm[];
    float* hs = sm;
    float* w1s = sm + 64 * Hn;
    __shared__ int s_aid[64];
    __shared__ int s_list[64];
    __shared__ int s_cnt;
    int t = threadIdx.x, lane = t & 31, warp = t >> 5;
    int b0 = blockIdx.x * 64;

    {
        const float4* src = (const float4*)(h + (size_t)b0 * Hn);
        float4* dst = (float4*)hs;
        for (int i = t; i < 64 * 128; i += 256) dst[i] = src[i];
    }
    if (t < 64) s_aid[t] = aid[b0 + t];
    __syncthreads();

    for (int a = 0; a < An; ++a) {
        if (t == 0) s_cnt = 0;
        __syncthreads();
        if (t < 64 && s_aid[t] == a) {
            int p = atomicAdd(&s_cnt, 1);
            s_list[p] = t;
        }
        __syncthreads();
        int cnt = s_cnt;
        if (cnt > 0) {
            const float4* wsrc = (const float4*)(w1 + (size_t)a * Hn * HH);
            float4* wdst = (float4*)w1s;
            for (int i = t; i < Hn * HH / 4; i += 256) wdst[i] = wsrc[i];
            __syncthreads();
            float w2v = w2[a * 32 + lane];
            float b1v = b1[a * 32 + lane];
            float b2v = b2[a];
            for (int s = warp * 2; s < cnt; s += 16) {
                int l0 = s_list[s];
                bool has1 = (s + 1 < cnt);
                int l1 = has1 ? s_list[s + 1] : l0;
                const float4* r0 = (const float4*)(hs + l0 * Hn);
                const float4* r1 = (const float4*)(hs + l1 * Hn);
                float a0 = 0.f, a1 = 0.f;
#pragma unroll 8
                for (int hq = 0; hq < 128; ++hq) {
                    float4 x0 = r0[hq];
                    float4 x1 = r1[hq];
                    float wv0 = w1s[(hq * 4 + 0) * 32 + lane];
                    float wv1 = w1s[(hq * 4 + 1) * 32 + lane];
                    float wv2 = w1s[(hq * 4 + 2) * 32 + lane];
                    float wv3 = w1s[(hq * 4 + 3) * 32 + lane];
                    a0 = fmaf(x0.x, wv0, a0); a0 = fmaf(x0.y, wv1, a0);
                    a0 = fmaf(x0.z, wv2, a0); a0 = fmaf(x0.w, wv3, a0);
                    a1 = fmaf(x1.x, wv0, a1); a1 = fmaf(x1.y, wv1, a1);
                    a1 = fmaf(x1.z, wv2, a1); a1 = fmaf(x1.w, wv3, a1);
                }
                float v0 = fmaxf(a0 + b1v, 0.f) * w2v;
                float v1 = fmaxf(a1 + b1v, 0.f) * w2v;
#pragma unroll
                for (int off = 16; off; off >>= 1) {
                    v0 += __shfl_xor_sync(0xFFFFFFFFu, v0, off);
                    v1 += __shfl_xor_sync(0xFFFFFFFFu, v1, off);
                }
                if (lane == 0) {
                    out[b0 + l0] = v0 + b2v;
                    if (has1) out[b0 + l1] = v1 + b2v;
                }
            }
            __syncthreads();
        } else {
            __syncthreads();
        }
    }
}

// ---------------- launch ----------------
extern "C" void kernel_launch(void* const* d_in, const int* in_sizes, int n_in,
                              void* d_out, int out_size) {
    const float* obs   = (const float*)d_in[0];
    const float* hprev = (const float*)d_in[1];
    const int*   aid   = (const int*)d_in[2];
    const float* pw0   = (const float*)d_in[3];
    const float* pb0   = (const float*)d_in[4];
    const float* pw1   = (const float*)d_in[5];
    const float* pb1   = (const float*)d_in[6];
    const float* wih   = (const float*)d_in[7];
    const float* whh   = (const float*)d_in[8];
    const float* bih   = (const float*)d_in[9];
    const float* bhh   = (const float*)d_in[10];
    const float* hw1   = (const float*)d_in[11];
    const float* hb1   = (const float*)d_in[12];
    const float* hw2   = (const float*)d_in[13];
    const float* hb2   = (const float*)d_in[14];

    float* out  = (float*)d_out;
    float* hout = out + Bn;

    cudaFuncSetAttribute(heads_kernel, cudaFuncAttributeMaxDynamicSharedMemorySize, 196608);
    cudaFuncSetAttribute(gemm2_bf_kernel, cudaFuncAttributeMaxDynamicSharedMemorySize, G2_SMEM);

    fold_wc_kernel<<<NE / 64, 256>>>(pw1, wih);
    fold_hh_kernel<<<NE * 32 / 256, 256>>>(whh);
    fold_bias_kernel<<<NE * 32 / 256, 256>>>(wih, pb1, bih, bhh);
    conv_h_kernel<<<(Bn * Hn / 8) / 256, 256>>>(hprev);
    gemm1_kernel<<<dim3(1, Bn / 64), 128>>>(obs, pw0, pb0);
    gemm2_bf_kernel<<<dim3(NE / 128, Bn / 128), 256, G2_SMEM>>>(hprev, hout);
    heads_kernel<<<Bn / 64, 256, 196608>>>(hout, aid, hw1, hb1, hw2, hb2, out);
}